// round 16
// baseline (speedup 1.0000x reference)
#include <cuda_runtime.h>
#include <cuda_fp16.h>
#include <cstdint>
#include <math.h>

#define NB   8      // batch
#define NI   8      // input capsules
#define CIN  16     // input capsule dim
#define HH   64
#define WWs  64
#define NO   8      // output capsules
#define DCAP 16     // output capsule dim
#define ODIM 128    // NO*DCAP
#define HWs  4096   // HH*WWs

// ---------------- device scratch (static: no runtime allocation) ----------------
__device__ __half g_uhat[(size_t)NI * NB * HWs * ODIM];   // [i][n][hw][od]  67MB fp16
__device__ __half g_uth [(size_t)NB * NI * HWs * CIN];    // [n][i][hw][c]   16.8MB fp16
__device__ uint2  g_w2f [(size_t)NI * 26 * 512];          // [i][pos][od*4+j] {b0,b1} (pos 25 = 0)
__device__ float g_b [(size_t)NI * NB * NO * HWs];        // [i][n][o][hw]   8MB
__device__ float g_bm[(size_t)NI * NB * HWs];             // windowed max    1MB
__device__ float g_ss[(size_t)NI * NB * HWs];             // boxsum of sum_o exp  1MB

__device__ __forceinline__ uint32_t pack_h2(float lo, float hi) {
    __half2 h = __floats2half2_rn(lo, hi);
    return *(uint32_t*)&h;
}

// =================================================================================
// Prep: transpose u to [n][i][hw][c] fp16.  Grid = 32; launched twice (blk0 = 0, 32)
// so that conv lands at launch index 3 (the ncu capture slot).
// =================================================================================
__global__ void __launch_bounds__(256) trans_kernel(const float* __restrict__ u, int blk0) {
    __shared__ float s[16 * 65];
    const int t = threadIdx.x;
    const int blk = blockIdx.x + blk0;                     // n*NI + i
    const float* src = u + (size_t)blk * CIN * HWs;
    __half* dst = g_uth + (size_t)blk * HWs * CIN;
    for (int h = 0; h < HH; h++) {
        #pragma unroll
        for (int j = 0; j < 4; j++) {
            int idx = t + j * 256;
            int c = idx >> 6, w = idx & 63;
            s[c * 65 + w] = src[(size_t)c * HWs + h * WWs + w];
        }
        __syncthreads();
        #pragma unroll
        for (int j = 0; j < 2; j++) {
            int idx = t + j * 256;          // 0..511 = 64 w x 8 cpair
            int w = idx >> 3, cp = idx & 7;
            uint32_t v = pack_h2(s[(2 * cp) * 65 + w], s[(2 * cp + 1) * 65 + w]);
            *(uint32_t*)(dst + ((size_t)h * WWs + w) * CIN + cp * 2) = v;
        }
        __syncthreads();
    }
}

// =================================================================================
// Prep: repack W into fp16 B-fragment order (pos 25 zero pad).
// =================================================================================
__global__ void __launch_bounds__(512) repack_kernel(const float* __restrict__ Wp) {
    const int i = blockIdx.x / 26, pos = blockIdx.x - i * 26;
    const int t = threadIdx.x;                // 0..511
    const int od = t >> 2, j = t & 3;
    uint2 v = make_uint2(0u, 0u);
    if (pos < 25) {
        // Wp layout: [i][od(128)][c(16)][25]
        const float* base = Wp + (((size_t)(i * 128 + od)) * 16) * 25 + pos;
        float c0 = base[(2 * j) * 25],     c1 = base[(2 * j + 1) * 25];
        float c2 = base[(2 * j + 8) * 25], c3 = base[(2 * j + 9) * 25];
        v.x = pack_h2(c0, c1); v.y = pack_h2(c2, c3);
    }
    g_w2f[(size_t)blockIdx.x * 512 + t] = v;
}

// =================================================================================
// Conv via mma.sync m16n8k16 fp16 (fp32 accumulate).
// CTA = (hp, n, i): M = 128 (rows h0,h0+1 x 64 w), N = 128 od, K = 400.
// Chunk = 2 positions (k32), 13 chunks, FULLY UNROLLED (compile-time pos/dh/dw).
// A: fp16 halo patch, pitch 24 halves; fragments via ldmatrix.m8n8.x4 (1 instr per
//    16x16 fragment; 48B row stride -> conflict-free phases).
// B: fragment-packed uint2, double-buffered.
// =================================================================================
#define PPITCH 24
#define PATCH_H (408 * PPITCH)   // 9792 halves = 19584 B

#define MMA_F16(d, a0, a1, a2, a3, b) \
    asm volatile("mma.sync.aligned.m16n8k16.row.col.f32.f16.f16.f32 " \
        "{%0,%1,%2,%3}, {%4,%5,%6,%7}, {%8,%9}, {%0,%1,%2,%3};" \
        : "+f"((d)[0]), "+f"((d)[1]), "+f"((d)[2]), "+f"((d)[3]) \
        : "r"(a0), "r"(a1), "r"(a2), "r"(a3), "r"((b).x), "r"((b).y))

#define LDSM_X4(r0, r1, r2, r3, addr) \
    asm volatile("ldmatrix.sync.aligned.m8n8.x4.shared.b16 {%0,%1,%2,%3}, [%4];" \
        : "=r"(r0), "=r"(r1), "=r"(r2), "=r"(r3) : "r"(addr))

__global__ void __launch_bounds__(256, 2) conv_mma_kernel() {
    __shared__ __align__(16) __half patch[PATCH_H];   // 19584 B
    __shared__ uint2 sB[2][1024];                     // 2 x 8192 B (2 positions/chunk)

    const int hp = blockIdx.x, nb = blockIdx.y, ic = blockIdx.z;
    const int h0 = hp * 2;
    const int t = threadIdx.x;
    const int lane = t & 31, wid = t >> 5;
    const int g = lane >> 2, tig = lane & 3;
    const int wm = wid & 3;        // 0..3 : m quarter (32 rows)
    const int wnn = wid >> 2;      // 0..1 : n half (64 cols)

    const __half* uth = g_uth + (size_t)(nb * NI + ic) * HWs * CIN;
    const uint2* wf = g_w2f + (size_t)ic * 26 * 512;

    // ---- stage halo patch: rows h0-2..h0+3, cols -2..65, zero padded ----
    #pragma unroll
    for (int j = 0; j < 4; j++) {
        int idx = j * 256 + t;               // uint4 item 0..815 (408 px x 2)
        if (idx < 816) {
            int pixel = idx >> 1, half8 = idx & 1;
            int hl = pixel / 68, wcol = pixel - hl * 68;
            int h = h0 - 2 + hl, w = wcol - 2;
            uint4 v = make_uint4(0u, 0u, 0u, 0u);
            if ((unsigned)h < 64u && (unsigned)w < 64u)
                v = *(const uint4*)(uth + ((size_t)h * WWs + w) * CIN + half8 * 8);
            *(uint4*)&patch[pixel * PPITCH + half8 * 8] = v;
        }
    }

    uint2 rbv[4];
    auto loadB = [&](int kt) {              // kt = chunk (2 positions)
        const uint2* src = wf + (size_t)kt * 1024;
        #pragma unroll
        for (int q = 0; q < 4; q++) rbv[q] = src[q * 256 + t];
    };
    auto stsB = [&](int buf) {
        #pragma unroll
        for (int q = 0; q < 4; q++) sB[buf][q * 256 + t] = rbv[q];
    };

    loadB(0);
    stsB(0);
    __syncthreads();        // patch + chunk 0 visible
    loadB(1);

    float acc[2][8][4];
    #pragma unroll
    for (int a = 0; a < 2; a++)
        #pragma unroll
        for (int b = 0; b < 8; b++)
            #pragma unroll
            for (int c = 0; c < 4; c++) acc[a][b][c] = 0.f;

    const int hbase = (wm >> 1);                 // 0/1 : which h row
    // ldmatrix lane -> (m row, k half) mapping offset, in halves
    const int laneoff = ((((lane >> 3) & 1) * 8) + (lane & 7)) * PPITCH + (lane >> 4) * 8;
    const uint32_t patch_smem =
        (uint32_t)__cvta_generic_to_shared(patch) + 2u * (uint32_t)laneoff;

    int buf = 0;
    #pragma unroll
    for (int kt = 0; kt < 13; kt++) {            // chunk = positions 2kt, 2kt+1
        #pragma unroll
        for (int s = 0; s < 2; s++) {
            const int pos = 2 * kt + s;
            if (pos < 25) {
                const int p5 = pos / 5;
                const int dh = p5 - 2, dw = pos - p5 * 5 - 2;
                // lane-invariant part of the A-tile base (halves)
                const int inv0 = ((hbase + dh + 2) * 68 + (wm & 1) * 32 + dw + 2) * PPITCH;

                uint32_t af[2][4];
                #pragma unroll
                for (int tm = 0; tm < 2; tm++) {
                    uint32_t addr = patch_smem + 2u * (uint32_t)(inv0 + tm * 16 * PPITCH);
                    LDSM_X4(af[tm][0], af[tm][1], af[tm][2], af[tm][3], addr);
                }
                uint2 bf[8];
                #pragma unroll
                for (int tn = 0; tn < 8; tn++)
                    bf[tn] = sB[buf][s * 512 + (wnn * 8 + tn) * 32 + lane];
                #pragma unroll
                for (int tm = 0; tm < 2; tm++)
                    #pragma unroll
                    for (int tn = 0; tn < 8; tn++)
                        MMA_F16(acc[tm][tn], af[tm][0], af[tm][1], af[tm][2], af[tm][3], bf[tn]);
            }
        }

        if (kt < 12) {
            stsB(buf ^ 1);
            __syncthreads();
            if (kt < 11) loadB(kt + 2);
            buf ^= 1;
        }
    }

    // epilogue -> fp16
    #pragma unroll
    for (int tm = 0; tm < 2; tm++) {
        #pragma unroll
        for (int tn = 0; tn < 8; tn++) {
            int row0 = wm * 32 + tm * 16 + g;
            int col  = wnn * 64 + tn * 8 + 2 * tig;
            #pragma unroll
            for (int rr = 0; rr < 2; rr++) {
                int row = row0 + rr * 8;
                int hh = row >> 6, w = row & 63;
                __half* ob = g_uhat +
                    ((((size_t)(ic * NB + nb) * HH + h0 + hh) * WWs + w) * ODIM + col);
                *(uint32_t*)ob = pack_h2(acc[tm][tn][rr * 2], acc[tm][tn][rr * 2 + 1]);
            }
        }
    }
}

// =================================================================================
// rkm: fused rk1+rk2+rk3-spatial. Block = (i,n) x 16-row band. Produces bm, ss.
// =================================================================================
__global__ void __launch_bounds__(256) rkm_kernel() {
    __shared__ float st [24][64];
    __shared__ float sbm[20][64];
    __shared__ float ssc[20][64];

    const int in = blockIdx.y;                // i*NB + n
    const int r0 = blockIdx.x * 16;
    const int t = threadIdx.x;
    const float* bb = g_b + (size_t)in * NO * HWs;

    // S1: t rows r0-4 .. r0+19
    #pragma unroll
    for (int k = 0; k < 6; k++) {
        int idx = k * 256 + t;                // 0..1535
        int row = idx >> 6, w = idx & 63;
        int h = r0 - 4 + row;
        float m = -3.4e38f;
        if ((unsigned)h < 64u) {
            const float* p = bb + h * 64 + w;
            #pragma unroll
            for (int o = 0; o < NO; o++) m = fmaxf(m, p[(size_t)o * HWs]);
        }
        st[row][w] = m;
    }
    __syncthreads();

    // S2: bm + sc rows r0-2 .. r0+17
    #pragma unroll
    for (int k = 0; k < 5; k++) {
        int idx = k * 256 + t;                // 0..1279
        int lr = idx >> 6, w = idx & 63;
        int h = r0 - 2 + lr;
        float m = -3.4e38f;
        #pragma unroll
        for (int dh = -2; dh <= 2; dh++) {
            #pragma unroll
            for (int dw = -2; dw <= 2; dw++) {
                int ww = w + dw;
                if ((unsigned)ww < 64u) m = fmaxf(m, st[lr + 2 + dh][ww]);
            }
        }
        float sc = 0.f;
        if ((unsigned)h < 64u) {
            const float* p = bb + h * 64 + w;
            #pragma unroll
            for (int o = 0; o < NO; o++) sc += __expf(p[(size_t)o * HWs] - m);
        }
        sbm[lr][w] = m;
        ssc[lr][w] = sc;
    }
    __syncthreads();

    // S3: ss rows r0 .. r0+15; write bm + ss
    #pragma unroll
    for (int k = 0; k < 4; k++) {
        int idx = k * 256 + t;                // 0..1023
        int lr2 = idx >> 6, w = idx & 63;
        int h = r0 + lr2;
        float ss = 0.f;
        #pragma unroll
        for (int dh = -2; dh <= 2; dh++) {
            #pragma unroll
            for (int dw = -2; dw <= 2; dw++) {
                int ww = w + dw;
                if ((unsigned)ww < 64u) ss += ssc[lr2 + 2 + dh][ww];
            }
        }
        g_bm[(size_t)in * HWs + h * 64 + w] = sbm[lr2 + 2][w];
        g_ss[(size_t)in * HWs + h * 64 + w] = ss;
    }
}

// =================================================================================
// pvb: b-update via Gram trick; r computed inline from (b, bm, ss). No smem.
// =================================================================================
__global__ void __launch_bounds__(128, 3) pvb_kernel(int mode) {
    const int t = threadIdx.x;
    const int o = t & 7, p = t >> 3;            // 16 pixels x 8 o per block
    const int P = blockIdx.x * 16 + p;
    const int n = P >> 12, hw = P & 4095;

    float r[8];
    if (mode == 0) {
        int h = hw >> 6, w = hw & 63;
        int ch = min(h + 2, HH - 1) - max(h - 2, 0) + 1;
        int cw = min(w + 2, WWs - 1) - max(w - 2, 0) + 1;
        float r0 = 1.f / (8.f * (float)(ch * cw));
        #pragma unroll
        for (int j = 0; j < 8; j++) r[j] = r0;
    } else {
        #pragma unroll
        for (int j = 0; j < 8; j++) {
            int in = j * NB + n;
            float bj  = g_b [((size_t)in * NO + o) * HWs + hw];
            float bmj = g_bm[(size_t)in * HWs + hw];
            float inv = 1.f / g_ss[(size_t)in * HWs + hw];
            r[j] = __expf(bj - bmj) * inv;
        }
    }

    float G[36];
    #pragma unroll
    for (int k = 0; k < 36; k++) G[k] = 0.f;

    const size_t ubase = ((size_t)n * HWs + hw) * ODIM + o * 16;
    const size_t istr = (size_t)NB * HWs * ODIM;
    #pragma unroll
    for (int d4 = 0; d4 < 4; d4++) {
        float4 u[8];
        #pragma unroll
        for (int i = 0; i < 8; i++) {
            uint2 v = *(const uint2*)(g_uhat + ubase + istr * i + d4 * 4);
            __half2* hp = (__half2*)&v;
            float2 f0 = __half22float2(hp[0]);
            float2 f1 = __half22float2(hp[1]);
            u[i] = make_float4(f0.x, f0.y, f1.x, f1.y);
        }
        int idx = 0;
        #pragma unroll
        for (int i = 0; i < 8; i++)
            #pragma unroll
            for (int j = i; j < 8; j++, idx++)
                G[idx] += u[i].x * u[j].x + u[i].y * u[j].y
                        + u[i].z * u[j].z + u[i].w * u[j].w;
    }

    float s[8];
    #pragma unroll
    for (int i = 0; i < 8; i++) s[i] = 0.f;
    {
        int idx = 0;
        #pragma unroll
        for (int i = 0; i < 8; i++)
            #pragma unroll
            for (int j = i; j < 8; j++, idx++) {
                s[i] += r[j] * G[idx];
                if (j > i) s[j] += r[i] * G[idx];
            }
    }
    float ns = 0.f;
    #pragma unroll
    for (int i = 0; i < 8; i++) ns += r[i] * s[i];
    float scale = ns / ((1.f + ns) * sqrtf(ns + 1e-9f));

    #pragma unroll
    for (int i = 0; i < 8; i++) {
        size_t bi = ((size_t)(i * NB + n) * NO + o) * HWs + hw;
        float a = scale * s[i];
        g_b[bi] = (mode == 0) ? a : g_b[bi] + a;
    }
}

// =================================================================================
// pvout: final iteration — r inline, stream p, squash, write fp32 output.
// =================================================================================
__global__ void __launch_bounds__(128, 4) pvout_kernel(float* __restrict__ out) {
    const int t = threadIdx.x;
    const int o = t & 7, p = t >> 3;
    const int P = blockIdx.x * 16 + p;
    const int n = P >> 12, hw = P & 4095;

    float r[8];
    #pragma unroll
    for (int j = 0; j < 8; j++) {
        int in = j * NB + n;
        float bj  = g_b [((size_t)in * NO + o) * HWs + hw];
        float bmj = g_bm[(size_t)in * HWs + hw];
        float inv = 1.f / g_ss[(size_t)in * HWs + hw];
        r[j] = __expf(bj - bmj) * inv;
    }

    float pv[16];
    #pragma unroll
    for (int d = 0; d < 16; d++) pv[d] = 0.f;

    const size_t ubase = ((size_t)n * HWs + hw) * ODIM + o * 16;
    const size_t istr = (size_t)NB * HWs * ODIM;
    #pragma unroll
    for (int d4 = 0; d4 < 4; d4++) {
        #pragma unroll
        for (int i = 0; i < 8; i++) {
            uint2 v = *(const uint2*)(g_uhat + ubase + istr * i + d4 * 4);
            __half2* hp = (__half2*)&v;
            float2 f0 = __half22float2(hp[0]);
            float2 f1 = __half22float2(hp[1]);
            pv[d4 * 4 + 0] += r[i] * f0.x;
            pv[d4 * 4 + 1] += r[i] * f0.y;
            pv[d4 * 4 + 2] += r[i] * f1.x;
            pv[d4 * 4 + 3] += r[i] * f1.y;
        }
    }

    float ns = 0.f;
    #pragma unroll
    for (int d = 0; d < 16; d++) ns += pv[d] * pv[d];
    float scale = ns / ((1.f + ns) * sqrtf(ns + 1e-9f));

    #pragma unroll
    for (int d = 0; d < 16; d++)
        out[(((size_t)n * NO + o) * DCAP + d) * HWs + hw] = pv[d] * scale;
}

// =================================================================================
extern "C" void kernel_launch(void* const* d_in, const int* in_sizes, int n_in,
                              void* d_out, int out_size) {
    const float* u  = (const float*)d_in[0];   // [8, 8, 16, 64, 64]
    const float* Wp = (const float*)d_in[1];   // [8, 128, 16, 5, 5]
    float* out = (float*)d_out;                // [8, 8, 16, 64, 64]

    repack_kernel<<<NI * 26, 512>>>(Wp);       // launch 0
    trans_kernel<<<32, 256>>>(u, 0);           // launch 1
    trans_kernel<<<32, 256>>>(u, 32);          // launch 2
    conv_mma_kernel<<<dim3(HH / 2, NB, NI), 256>>>();   // launch 3 (profiled)

    // routing iteration 0 (b = 0 -> analytic r)
    pvb_kernel<<<NB * HWs / 16, 128>>>(0);

    // routing iteration 1
    rkm_kernel<<<dim3(4, NI * NB), 256>>>();
    pvb_kernel<<<NB * HWs / 16, 128>>>(1);

    // routing iteration 2 (final output)
    rkm_kernel<<<dim3(4, NI * NB), 256>>>();
    pvout_kernel<<<NB * HWs / 16, 128>>>(out);
}

// round 17
// speedup vs baseline: 1.1505x; 1.1505x over previous
#include <cuda_runtime.h>
#include <cuda_fp16.h>
#include <cstdint>
#include <math.h>

#define NB   8      // batch
#define NI   8      // input capsules
#define CIN  16     // input capsule dim
#define HH   64
#define WWs  64
#define NO   8      // output capsules
#define DCAP 16     // output capsule dim
#define ODIM 128    // NO*DCAP
#define HWs  4096   // HH*WWs

// ---------------- device scratch (static: no runtime allocation) ----------------
__device__ __half g_uhat[(size_t)NI * NB * HWs * ODIM];   // [i][n][hw][od]  67MB fp16
__device__ __half g_uth [(size_t)NB * NI * HWs * CIN];    // [n][i][hw][c]   16.8MB fp16
__device__ uint2  g_w2f [(size_t)NI * 25 * 512];          // [i][pos][od*4+j] {b0,b1}
__device__ float g_b [(size_t)NI * NB * NO * HWs];        // [i][n][o][hw]   8MB
__device__ float g_bm[(size_t)NI * NB * HWs];             // windowed max    1MB
__device__ float g_ss[(size_t)NI * NB * HWs];             // boxsum of sum_o exp  1MB

// position -> (pos/5)*68 + pos%5  (halo-row * 68 + halo-col)
__constant__ int c_off[25] = {
      0,   1,   2,   3,   4,
     68,  69,  70,  71,  72,
    136, 137, 138, 139, 140,
    204, 205, 206, 207, 208,
    272, 273, 274, 275, 276
};

__device__ __forceinline__ uint32_t pack_h2(float lo, float hi) {
    __half2 h = __floats2half2_rn(lo, hi);
    return *(uint32_t*)&h;
}

// =================================================================================
// Prep: transpose u to [n][i][hw][c] fp16 (single launch)
// =================================================================================
__global__ void __launch_bounds__(256) trans_kernel(const float* __restrict__ u) {
    __shared__ float s[16 * 65];
    const int t = threadIdx.x;
    const float* src = u + (size_t)blockIdx.x * CIN * HWs;   // blockIdx = n*NI+i
    __half* dst = g_uth + (size_t)blockIdx.x * HWs * CIN;
    for (int h = 0; h < HH; h++) {
        #pragma unroll
        for (int j = 0; j < 4; j++) {
            int idx = t + j * 256;
            int c = idx >> 6, w = idx & 63;
            s[c * 65 + w] = src[(size_t)c * HWs + h * WWs + w];
        }
        __syncthreads();
        #pragma unroll
        for (int j = 0; j < 2; j++) {
            int idx = t + j * 256;          // 0..511 = 64 w x 8 cpair
            int w = idx >> 3, cp = idx & 7;
            uint32_t v = pack_h2(s[(2 * cp) * 65 + w], s[(2 * cp + 1) * 65 + w]);
            *(uint32_t*)(dst + ((size_t)h * WWs + w) * CIN + cp * 2) = v;
        }
        __syncthreads();
    }
}

// =================================================================================
// Prep: repack W into fp16 B-fragment order. Grid 100/launch, launched twice
// (blk0 = 0, 100) so conv lands at ncu capture slot 3.
// =================================================================================
__global__ void __launch_bounds__(512) repack_kernel(const float* __restrict__ Wp, int blk0) {
    const int blk = blockIdx.x + blk0;        // i*25 + pos
    const int i = blk / 25, pos = blk - i * 25;
    const int t = threadIdx.x;                // 0..511
    const int od = t >> 2, j = t & 3;
    // Wp layout: [i][od(128)][c(16)][25]
    const float* base = Wp + (((size_t)(i * 128 + od)) * 16) * 25 + pos;
    float c0 = base[(2 * j) * 25],     c1 = base[(2 * j + 1) * 25];
    float c2 = base[(2 * j + 8) * 25], c3 = base[(2 * j + 9) * 25];
    uint2 v; v.x = pack_h2(c0, c1); v.y = pack_h2(c2, c3);
    g_w2f[(size_t)blk * 512 + t] = v;
}

// =================================================================================
// Conv via mma.sync m16n8k16 fp16 (fp32 accumulate).
// CTA = (hp, n, i): M = 128 (rows h0,h0+1 x 64 w), N = 128 od, K = 400.
// A: fp16 halo patch in smem (pitch 24 halves), fragments via ldmatrix.m8n8.x4.
// B: fetched DIRECTLY from global (L2-resident fragment-packed table) — no smem
//    staging, no double buffer, and NO __syncthreads in the main loop.
// Rolled 25-position loop; offsets from compile-time __constant__ table.
// =================================================================================
#define PPITCH 24
#define PATCH_H (408 * PPITCH)   // 9792 halves = 19584 B

#define MMA_F16(d, a0, a1, a2, a3, b) \
    asm volatile("mma.sync.aligned.m16n8k16.row.col.f32.f16.f16.f32 " \
        "{%0,%1,%2,%3}, {%4,%5,%6,%7}, {%8,%9}, {%0,%1,%2,%3};" \
        : "+f"((d)[0]), "+f"((d)[1]), "+f"((d)[2]), "+f"((d)[3]) \
        : "r"(a0), "r"(a1), "r"(a2), "r"(a3), "r"((b).x), "r"((b).y))

#define LDSM_X4(r0, r1, r2, r3, addr) \
    asm volatile("ldmatrix.sync.aligned.m8n8.x4.shared.b16 {%0,%1,%2,%3}, [%4];" \
        : "=r"(r0), "=r"(r1), "=r"(r2), "=r"(r3) : "r"(addr))

__global__ void __launch_bounds__(256, 2) conv_mma_kernel() {
    __shared__ __align__(16) __half patch[PATCH_H];   // 19584 B (only smem)

    const int hp = blockIdx.x, nb = blockIdx.y, ic = blockIdx.z;
    const int h0 = hp * 2;
    const int t = threadIdx.x;
    const int lane = t & 31, wid = t >> 5;
    const int g = lane >> 2, tig = lane & 3;
    const int wm = wid & 3;        // 0..3 : m quarter (32 rows)
    const int wnn = wid >> 2;      // 0..1 : n half (64 cols)

    const __half* uth = g_uth + (size_t)(nb * NI + ic) * HWs * CIN;
    const uint2* wf = g_w2f + (size_t)ic * 25 * 512 + (wnn * 8) * 32 + lane;

    // ---- stage input halo patch: rows h0-2..h0+3, cols -2..65, zero padded ----
    #pragma unroll
    for (int j = 0; j < 4; j++) {
        int idx = j * 256 + t;               // uint4 item 0..815 (408 px x 2)
        if (idx < 816) {
            int pixel = idx >> 1, half8 = idx & 1;
            int hl = pixel / 68, wcol = pixel - hl * 68;
            int h = h0 - 2 + hl, w = wcol - 2;
            uint4 v = make_uint4(0u, 0u, 0u, 0u);
            if ((unsigned)h < 64u && (unsigned)w < 64u)
                v = *(const uint4*)(uth + ((size_t)h * WWs + w) * CIN + half8 * 8);
            *(uint4*)&patch[pixel * PPITCH + half8 * 8] = v;
        }
    }
    __syncthreads();        // patch visible; no further barriers

    float acc[2][8][4];
    #pragma unroll
    for (int a = 0; a < 2; a++)
        #pragma unroll
        for (int b = 0; b < 8; b++)
            #pragma unroll
            for (int c = 0; c < 4; c++) acc[a][b][c] = 0.f;

    // base halo pixel (before per-position offset) and ldmatrix lane offset
    const int pbase = (wm >> 1) * 68 + (wm & 1) * 32;
    const int laneoff = ((((lane >> 3) & 1) * 8) + (lane & 7)) * PPITCH + (lane >> 4) * 8;
    const uint32_t patch_smem =
        (uint32_t)__cvta_generic_to_shared(patch) + 2u * (uint32_t)laneoff;

    for (int pos = 0; pos < 25; pos++) {
        // B fragments straight from global (L2/L1-resident table)
        uint2 bf[8];
        const uint2* wp = wf + (size_t)pos * 512;
        #pragma unroll
        for (int tn = 0; tn < 8; tn++) bf[tn] = __ldg(wp + tn * 32);

        const int prow = pbase + c_off[pos];
        uint32_t af[2][4];
        #pragma unroll
        for (int tm = 0; tm < 2; tm++) {
            uint32_t addr = patch_smem + 2u * (uint32_t)((prow + tm * 16) * PPITCH);
            LDSM_X4(af[tm][0], af[tm][1], af[tm][2], af[tm][3], addr);
        }
        #pragma unroll
        for (int tm = 0; tm < 2; tm++)
            #pragma unroll
            for (int tn = 0; tn < 8; tn++)
                MMA_F16(acc[tm][tn], af[tm][0], af[tm][1], af[tm][2], af[tm][3], bf[tn]);
    }

    // epilogue -> fp16
    #pragma unroll
    for (int tm = 0; tm < 2; tm++) {
        #pragma unroll
        for (int tn = 0; tn < 8; tn++) {
            int row0 = wm * 32 + tm * 16 + g;
            int col  = wnn * 64 + tn * 8 + 2 * tig;
            #pragma unroll
            for (int rr = 0; rr < 2; rr++) {
                int row = row0 + rr * 8;
                int hh = row >> 6, w = row & 63;
                __half* ob = g_uhat +
                    ((((size_t)(ic * NB + nb) * HH + h0 + hh) * WWs + w) * ODIM + col);
                *(uint32_t*)ob = pack_h2(acc[tm][tn][rr * 2], acc[tm][tn][rr * 2 + 1]);
            }
        }
    }
}

// =================================================================================
// rkm: fused rk1+rk2+rk3-spatial. Block = (i,n) x 16-row band. Produces bm, ss.
// =================================================================================
__global__ void __launch_bounds__(256) rkm_kernel() {
    __shared__ float st [24][64];
    __shared__ float sbm[20][64];
    __shared__ float ssc[20][64];

    const int in = blockIdx.y;                // i*NB + n
    const int r0 = blockIdx.x * 16;
    const int t = threadIdx.x;
    const float* bb = g_b + (size_t)in * NO * HWs;

    // S1: t rows r0-4 .. r0+19
    #pragma unroll
    for (int k = 0; k < 6; k++) {
        int idx = k * 256 + t;                // 0..1535
        int row = idx >> 6, w = idx & 63;
        int h = r0 - 4 + row;
        float m = -3.4e38f;
        if ((unsigned)h < 64u) {
            const float* p = bb + h * 64 + w;
            #pragma unroll
            for (int o = 0; o < NO; o++) m = fmaxf(m, p[(size_t)o * HWs]);
        }
        st[row][w] = m;
    }
    __syncthreads();

    // S2: bm + sc rows r0-2 .. r0+17
    #pragma unroll
    for (int k = 0; k < 5; k++) {
        int idx = k * 256 + t;                // 0..1279
        int lr = idx >> 6, w = idx & 63;
        int h = r0 - 2 + lr;
        float m = -3.4e38f;
        #pragma unroll
        for (int dh = -2; dh <= 2; dh++) {
            #pragma unroll
            for (int dw = -2; dw <= 2; dw++) {
                int ww = w + dw;
                if ((unsigned)ww < 64u) m = fmaxf(m, st[lr + 2 + dh][ww]);
            }
        }
        float sc = 0.f;
        if ((unsigned)h < 64u) {
            const float* p = bb + h * 64 + w;
            #pragma unroll
            for (int o = 0; o < NO; o++) sc += __expf(p[(size_t)o * HWs] - m);
        }
        sbm[lr][w] = m;
        ssc[lr][w] = sc;
    }
    __syncthreads();

    // S3: ss rows r0 .. r0+15; write bm + ss
    #pragma unroll
    for (int k = 0; k < 4; k++) {
        int idx = k * 256 + t;                // 0..1023
        int lr2 = idx >> 6, w = idx & 63;
        int h = r0 + lr2;
        float ss = 0.f;
        #pragma unroll
        for (int dh = -2; dh <= 2; dh++) {
            #pragma unroll
            for (int dw = -2; dw <= 2; dw++) {
                int ww = w + dw;
                if ((unsigned)ww < 64u) ss += ssc[lr2 + 2 + dh][ww];
            }
        }
        g_bm[(size_t)in * HWs + h * 64 + w] = sbm[lr2 + 2][w];
        g_ss[(size_t)in * HWs + h * 64 + w] = ss;
    }
}

// =================================================================================
// pvb: b-update via Gram trick; r computed inline from (b, bm, ss). No smem.
// =================================================================================
__global__ void __launch_bounds__(128, 3) pvb_kernel(int mode) {
    const int t = threadIdx.x;
    const int o = t & 7, p = t >> 3;            // 16 pixels x 8 o per block
    const int P = blockIdx.x * 16 + p;
    const int n = P >> 12, hw = P & 4095;

    float r[8];
    if (mode == 0) {
        int h = hw >> 6, w = hw & 63;
        int ch = min(h + 2, HH - 1) - max(h - 2, 0) + 1;
        int cw = min(w + 2, WWs - 1) - max(w - 2, 0) + 1;
        float r0 = 1.f / (8.f * (float)(ch * cw));
        #pragma unroll
        for (int j = 0; j < 8; j++) r[j] = r0;
    } else {
        #pragma unroll
        for (int j = 0; j < 8; j++) {
            int in = j * NB + n;
            float bj  = g_b [((size_t)in * NO + o) * HWs + hw];
            float bmj = g_bm[(size_t)in * HWs + hw];
            float inv = 1.f / g_ss[(size_t)in * HWs + hw];
            r[j] = __expf(bj - bmj) * inv;
        }
    }

    float G[36];
    #pragma unroll
    for (int k = 0; k < 36; k++) G[k] = 0.f;

    const size_t ubase = ((size_t)n * HWs + hw) * ODIM + o * 16;
    const size_t istr = (size_t)NB * HWs * ODIM;
    #pragma unroll
    for (int d4 = 0; d4 < 4; d4++) {
        float4 u[8];
        #pragma unroll
        for (int i = 0; i < 8; i++) {
            uint2 v = *(const uint2*)(g_uhat + ubase + istr * i + d4 * 4);
            __half2* hp = (__half2*)&v;
            float2 f0 = __half22float2(hp[0]);
            float2 f1 = __half22float2(hp[1]);
            u[i] = make_float4(f0.x, f0.y, f1.x, f1.y);
        }
        int idx = 0;
        #pragma unroll
        for (int i = 0; i < 8; i++)
            #pragma unroll
            for (int j = i; j < 8; j++, idx++)
                G[idx] += u[i].x * u[j].x + u[i].y * u[j].y
                        + u[i].z * u[j].z + u[i].w * u[j].w;
    }

    float s[8];
    #pragma unroll
    for (int i = 0; i < 8; i++) s[i] = 0.f;
    {
        int idx = 0;
        #pragma unroll
        for (int i = 0; i < 8; i++)
            #pragma unroll
            for (int j = i; j < 8; j++, idx++) {
                s[i] += r[j] * G[idx];
                if (j > i) s[j] += r[i] * G[idx];
            }
    }
    float ns = 0.f;
    #pragma unroll
    for (int i = 0; i < 8; i++) ns += r[i] * s[i];
    float scale = ns / ((1.f + ns) * sqrtf(ns + 1e-9f));

    #pragma unroll
    for (int i = 0; i < 8; i++) {
        size_t bi = ((size_t)(i * NB + n) * NO + o) * HWs + hw;
        float a = scale * s[i];
        g_b[bi] = (mode == 0) ? a : g_b[bi] + a;
    }
}

// =================================================================================
// pvout: final iteration — r inline, stream p, squash, write fp32 output.
// =================================================================================
__global__ void __launch_bounds__(128, 4) pvout_kernel(float* __restrict__ out) {
    const int t = threadIdx.x;
    const int o = t & 7, p = t >> 3;
    const int P = blockIdx.x * 16 + p;
    const int n = P >> 12, hw = P & 4095;

    float r[8];
    #pragma unroll
    for (int j = 0; j < 8; j++) {
        int in = j * NB + n;
        float bj  = g_b [((size_t)in * NO + o) * HWs + hw];
        float bmj = g_bm[(size_t)in * HWs + hw];
        float inv = 1.f / g_ss[(size_t)in * HWs + hw];
        r[j] = __expf(bj - bmj) * inv;
    }

    float pv[16];
    #pragma unroll
    for (int d = 0; d < 16; d++) pv[d] = 0.f;

    const size_t ubase = ((size_t)n * HWs + hw) * ODIM + o * 16;
    const size_t istr = (size_t)NB * HWs * ODIM;
    #pragma unroll
    for (int d4 = 0; d4 < 4; d4++) {
        #pragma unroll
        for (int i = 0; i < 8; i++) {
            uint2 v = *(const uint2*)(g_uhat + ubase + istr * i + d4 * 4);
            __half2* hp = (__half2*)&v;
            float2 f0 = __half22float2(hp[0]);
            float2 f1 = __half22float2(hp[1]);
            pv[d4 * 4 + 0] += r[i] * f0.x;
            pv[d4 * 4 + 1] += r[i] * f0.y;
            pv[d4 * 4 + 2] += r[i] * f1.x;
            pv[d4 * 4 + 3] += r[i] * f1.y;
        }
    }

    float ns = 0.f;
    #pragma unroll
    for (int d = 0; d < 16; d++) ns += pv[d] * pv[d];
    float scale = ns / ((1.f + ns) * sqrtf(ns + 1e-9f));

    #pragma unroll
    for (int d = 0; d < 16; d++)
        out[(((size_t)n * NO + o) * DCAP + d) * HWs + hw] = pv[d] * scale;
}

// =================================================================================
extern "C" void kernel_launch(void* const* d_in, const int* in_sizes, int n_in,
                              void* d_out, int out_size) {
    const float* u  = (const float*)d_in[0];   // [8, 8, 16, 64, 64]
    const float* Wp = (const float*)d_in[1];   // [8, 128, 16, 5, 5]
    float* out = (float*)d_out;                // [8, 8, 16, 64, 64]

    repack_kernel<<<100, 512>>>(Wp, 0);        // launch 0
    repack_kernel<<<100, 512>>>(Wp, 100);      // launch 1
    trans_kernel<<<NB * NI, 256>>>(u);         // launch 2
    conv_mma_kernel<<<dim3(HH / 2, NB, NI), 256>>>();   // launch 3 (profiled)

    // routing iteration 0 (b = 0 -> analytic r)
    pvb_kernel<<<NB * HWs / 16, 128>>>(0);

    // routing iteration 1
    rkm_kernel<<<dim3(4, NI * NB), 256>>>();
    pvb_kernel<<<NB * HWs / 16, 128>>>(1);

    // routing iteration 2 (final output)
    rkm_kernel<<<dim3(4, NI * NB), 256>>>();
    pvout_kernel<<<NB * HWs / 16, 128>>>(out);
}